// round 11
// baseline (speedup 1.0000x reference)
#include <cuda_runtime.h>
#include <cuda_bf16.h>

#define NN 50000
#define EE 800000

// Scratch (no cudaMalloc allowed)
__device__ float g_ht[NN * 128];   // h @ W_node, [N][H*F]
__device__ float g_ss[NN * 8];     // per-node src attention scalar
__device__ float g_sd[NN * 8];     // per-node dst attention scalar
__device__ float g_se[NN * 8];     // sum of exp per (dst, head)
__device__ uint4 g_Bhi[2048];      // W^T hi bf16, [n=128][k=128] (32KB)
__device__ uint4 g_Blo[2048];      // W^T lo bf16
__device__ int   g_cnt[NN];        // per-src edge count
__device__ int   g_off[NN];        // block-local exclusive scan
__device__ int   g_bsum[256];      // block sums / exclusive block prefix
__device__ int   g_cur[NN];        // final start offsets (consumed by scatter)
__device__ int   g_es[EE];         // src sorted by src
__device__ int   g_ed[EE];         // dst sorted by src
__device__ float g_eef[EE];        // edge feat sorted by src

// ---------------- helpers ----------------
__device__ __forceinline__ void red_add_v4(float* p, float4 v) {
    asm volatile("red.global.add.v4.f32 [%0], {%1,%2,%3,%4};"
                 :: "l"(p), "f"(v.x), "f"(v.y), "f"(v.z), "f"(v.w) : "memory");
}
__device__ __forceinline__ unsigned smem_u32(const void* p) {
    unsigned a;
    asm("{ .reg .u64 t; cvta.to.shared.u64 t, %1; cvt.u32.u64 %0, t; }"
        : "=r"(a) : "l"(p));
    return a;
}
__device__ __forceinline__ void ldsm4(unsigned* r, unsigned addr) {
    asm volatile("ldmatrix.sync.aligned.m8n8.x4.shared.b16 {%0,%1,%2,%3}, [%4];"
                 : "=r"(r[0]), "=r"(r[1]), "=r"(r[2]), "=r"(r[3]) : "r"(addr));
}
__device__ __forceinline__ void mma_bf16(float* d, const unsigned* a,
                                         unsigned b0, unsigned b1) {
    asm volatile(
        "mma.sync.aligned.m16n8k16.row.col.f32.bf16.bf16.f32 "
        "{%0,%1,%2,%3}, {%4,%5,%6,%7}, {%8,%9}, {%0,%1,%2,%3};"
        : "+f"(d[0]), "+f"(d[1]), "+f"(d[2]), "+f"(d[3])
        : "r"(a[0]), "r"(a[1]), "r"(a[2]), "r"(a[3]), "r"(b0), "r"(b1));
}
__device__ __forceinline__ int swz(int c, int r) {
    return (c & 8) | ((c ^ r) & 7);
}

// ---------------------------------------------------------------------------
// K0: prepack W^T hi/lo bf16 (B[n][k] = W[k][n]).
// ---------------------------------------------------------------------------
__global__ void k_prepW(const float* __restrict__ Wn) {
    int idx = blockIdx.x * 256 + threadIdx.x;
    if (idx >= 128 * 128) return;
    int n = idx >> 7, k = idx & 127;
    float v = Wn[k * 128 + n];
    __nv_bfloat16 hi = __float2bfloat16(v);
    __nv_bfloat16 lo = __float2bfloat16(v - __bfloat162float(hi));
    ((__nv_bfloat16*)g_Bhi)[n * 128 + k] = hi;
    ((__nv_bfloat16*)g_Blo)[n * 128 + k] = lo;
}

// ---------------------------------------------------------------------------
// Counting sort of edges by src (key = src node id, 50000 counters).
// ---------------------------------------------------------------------------
__global__ void k_hist(const int* __restrict__ ei) {
    int e = blockIdx.x * 256 + threadIdx.x;   // EE % 256 == 0
    atomicAdd(&g_cnt[ei[e]], 1);
}

// block-local exclusive scan of g_cnt -> g_off, block totals -> g_bsum
__global__ void k_scanA() {
    __shared__ int sh[256];
    int i = blockIdx.x * 256 + threadIdx.x;
    int v = (i < NN) ? g_cnt[i] : 0;
    sh[threadIdx.x] = v;
    __syncthreads();
#pragma unroll
    for (int o = 1; o < 256; o <<= 1) {
        int t = (threadIdx.x >= o) ? sh[threadIdx.x - o] : 0;
        __syncthreads();
        sh[threadIdx.x] += t;
        __syncthreads();
    }
    if (i < NN) g_off[i] = sh[threadIdx.x] - v;
    if (threadIdx.x == 255) g_bsum[blockIdx.x] = sh[255];
}

// scan the 196 block sums (one block)
__global__ void k_scanB() {
    __shared__ int sh[256];
    int v = (threadIdx.x < 196) ? g_bsum[threadIdx.x] : 0;
    sh[threadIdx.x] = v;
    __syncthreads();
#pragma unroll
    for (int o = 1; o < 256; o <<= 1) {
        int t = (threadIdx.x >= o) ? sh[threadIdx.x - o] : 0;
        __syncthreads();
        sh[threadIdx.x] += t;
        __syncthreads();
    }
    g_bsum[threadIdx.x] = sh[threadIdx.x] - v;   // exclusive
}

// combine: final start offsets into g_cur
__global__ void k_scanC() {
    int i = blockIdx.x * 256 + threadIdx.x;
    if (i < NN) g_cur[i] = g_off[i] + g_bsum[i >> 8];
}

__global__ void k_scat(const int* __restrict__ ei,
                       const float* __restrict__ ef) {
    int e = blockIdx.x * 256 + threadIdx.x;
    int s = ei[e];
    int d = ei[EE + e];
    float f = ef[e];
    int pos = atomicAdd(&g_cur[s], 1);
    g_es[pos] = s;
    g_ed[pos] = d;
    g_eef[pos] = f;
}

// ---------------------------------------------------------------------------
// K1: bf16 3-term GEMM via mma.sync (D = Ahi*Bhi + Ahi*Blo + Alo*Bhi)
// + FUSED s_src/s_dst epilogue.
// ---------------------------------------------------------------------------
#define SM_AHI 0
#define SM_ALO 16384
#define SM_BHI 32768
#define SM_BLO 65536
#define SM_TOT 98304

__global__ __launch_bounds__(256, 2) void k_gemm(const float* __restrict__ hin,
                                                 const float* __restrict__ asrc,
                                                 const float* __restrict__ adst) {
    extern __shared__ char sm[];
    const unsigned sb = smem_u32(sm);
    const int tid = threadIdx.x, wid = tid >> 5, lid = tid & 31;
    const int n0 = blockIdx.x << 6;

#pragma unroll
    for (int i = 0; i < 8; i++) {
        int idx = tid + i * 256;
        int r = idx >> 4, c = idx & 15;
        int off = r * 256 + swz(c, r & 7) * 16;
        *(uint4*)(sm + SM_BHI + off) = g_Bhi[idx];
        *(uint4*)(sm + SM_BLO + off) = g_Blo[idx];
    }
    const float4* h4 = (const float4*)hin;
#pragma unroll
    for (int i = 0; i < 8; i++) {
        int idx = tid + i * 256;
        int r = idx >> 5, c4 = idx & 31;
        int k = c4 << 2;
        float4 v = make_float4(0.f, 0.f, 0.f, 0.f);
        if (n0 + r < NN) v = h4[(size_t)(n0 + r) * 32 + c4];
        __nv_bfloat162 hA = __floats2bfloat162_rn(v.x, v.y);
        __nv_bfloat162 hB = __floats2bfloat162_rn(v.z, v.w);
        __nv_bfloat162 lA = __floats2bfloat162_rn(v.x - __bfloat162float(hA.x),
                                                  v.y - __bfloat162float(hA.y));
        __nv_bfloat162 lB = __floats2bfloat162_rn(v.z - __bfloat162float(hB.x),
                                                  v.w - __bfloat162float(hB.y));
        int off = r * 256 + swz(k >> 3, r & 7) * 16 + (k & 7) * 2;
        *(uint2*)(sm + SM_AHI + off) = make_uint2(*(unsigned*)&hA, *(unsigned*)&hB);
        *(uint2*)(sm + SM_ALO + off) = make_uint2(*(unsigned*)&lA, *(unsigned*)&lB);
    }
    __syncthreads();

    const int rh = wid & 3;
    const int ch = wid >> 2;

    float acc[8][4];
#pragma unroll
    for (int t = 0; t < 8; t++)
#pragma unroll
        for (int j = 0; j < 4; j++) acc[t][j] = 0.f;

    const int arow = rh * 16 + (lid & 15);
    const int bl = (lid & 7) + ((lid >> 4) << 3);
    const int bko = (lid >> 3) & 1;

#pragma unroll
    for (int ks = 0; ks < 8; ks++) {
        unsigned ahi[4], alo[4];
        {
            int c = ks * 2 + (lid >> 4);
            int aoff = arow * 256 + swz(c, arow & 7) * 16;
            ldsm4(ahi, sb + SM_AHI + aoff);
            ldsm4(alo, sb + SM_ALO + aoff);
        }
#pragma unroll
        for (int p = 0; p < 4; p++) {
            int n = ch * 64 + p * 16 + bl;
            int c = ks * 2 + bko;
            int boff = n * 256 + swz(c, n & 7) * 16;
            unsigned bhi[4], blo[4];
            ldsm4(bhi, sb + SM_BHI + boff);
            ldsm4(blo, sb + SM_BLO + boff);
            mma_bf16(acc[2 * p],     ahi, bhi[0], bhi[1]);
            mma_bf16(acc[2 * p],     ahi, blo[0], blo[1]);
            mma_bf16(acc[2 * p],     alo, bhi[0], bhi[1]);
            mma_bf16(acc[2 * p + 1], ahi, bhi[2], bhi[3]);
            mma_bf16(acc[2 * p + 1], ahi, blo[2], blo[3]);
            mma_bf16(acc[2 * p + 1], alo, bhi[2], bhi[3]);
        }
    }

    const int r0 = n0 + rh * 16 + (lid >> 2);
    const int r1 = r0 + 8;
#pragma unroll
    for (int t = 0; t < 8; t++) {
        int gcol = ch * 64 + t * 8 + 2 * (lid & 3);
        if (r0 < NN) *(float2*)(g_ht + (size_t)r0 * 128 + gcol) =
            make_float2(acc[t][0], acc[t][1]);
        if (r1 < NN) *(float2*)(g_ht + (size_t)r1 * 128 + gcol) =
            make_float2(acc[t][2], acc[t][3]);
    }
    const int q2 = 2 * (lid & 3);
#pragma unroll
    for (int u = 0; u < 4; u++) {
        int hh = ch * 4 + u;
        const float* as = asrc + hh * 16;
        const float* ad = adst + hh * 16;
        float a0 = __ldg(as + q2),     a1 = __ldg(as + q2 + 1);
        float a2 = __ldg(as + 8 + q2), a3 = __ldg(as + 8 + q2 + 1);
        float b0 = __ldg(ad + q2),     b1 = __ldg(ad + q2 + 1);
        float b2 = __ldg(ad + 8 + q2), b3 = __ldg(ad + 8 + q2 + 1);
        float s0 = acc[2*u][0]*a0 + acc[2*u][1]*a1 + acc[2*u+1][0]*a2 + acc[2*u+1][1]*a3;
        float s1 = acc[2*u][2]*a0 + acc[2*u][3]*a1 + acc[2*u+1][2]*a2 + acc[2*u+1][3]*a3;
        float d0 = acc[2*u][0]*b0 + acc[2*u][1]*b1 + acc[2*u+1][0]*b2 + acc[2*u+1][1]*b3;
        float d1 = acc[2*u][2]*b0 + acc[2*u][3]*b1 + acc[2*u+1][2]*b2 + acc[2*u+1][3]*b3;
        s0 += __shfl_xor_sync(0xffffffffu, s0, 1);
        s0 += __shfl_xor_sync(0xffffffffu, s0, 2);
        s1 += __shfl_xor_sync(0xffffffffu, s1, 1);
        s1 += __shfl_xor_sync(0xffffffffu, s1, 2);
        d0 += __shfl_xor_sync(0xffffffffu, d0, 1);
        d0 += __shfl_xor_sync(0xffffffffu, d0, 2);
        d1 += __shfl_xor_sync(0xffffffffu, d1, 1);
        d1 += __shfl_xor_sync(0xffffffffu, d1, 2);
        if ((lid & 3) == 0) {
            if (r0 < NN) { g_ss[r0 * 8 + hh] = s0; g_sd[r0 * 8 + hh] = d0; }
            if (r1 < NN) { g_ss[r1 * 8 + hh] = s1; g_sd[r1 * 8 + hh] = d1; }
        }
    }
}

// ---------------------------------------------------------------------------
// K3: edge pass A on src-sorted edges — sum of exp per (dst, head).
// ---------------------------------------------------------------------------
__global__ void k_edgeA(const float* __restrict__ We) {
    int gid = blockIdx.x * 256 + threadIdx.x;   // (EE*2) % 256 == 0
    int e = gid >> 1;
    int half = gid & 1;
    int src = g_es[e];
    int dst = g_ed[e];
    float f = g_eef[e];
    float4 s = ((const float4*)g_ss)[src * 2 + half];
    float4 d = ((const float4*)g_sd)[dst * 2 + half];
    float4 w = ((const float4*)We)[half];
    float4 x;
    x.x = s.x + d.x + f * w.x;
    x.y = s.y + d.y + f * w.y;
    x.z = s.z + d.z + f * w.z;
    x.w = s.w + d.w + f * w.w;
    x.x = __expf(fmaxf(x.x, 0.2f * x.x));
    x.y = __expf(fmaxf(x.y, 0.2f * x.y));
    x.z = __expf(fmaxf(x.z, 0.2f * x.z));
    x.w = __expf(fmaxf(x.w, 0.2f * x.w));
    red_add_v4(g_se + dst * 8 + half * 4, x);
}

// ---------------------------------------------------------------------------
// K4: edge pass B on src-sorted edges — same-src edges adjacent => g_ht
// gathers hit L1. 8 lanes/edge, 4x red.v4 per edge.
// ---------------------------------------------------------------------------
__global__ void k_edgeB(const float* __restrict__ We,
                        float* __restrict__ out) {
    int gid = blockIdx.x * 256 + threadIdx.x;  // (EE*8) % 256 == 0
    int e = gid >> 3;
    int l = gid & 7;
    int src = g_es[e];
    int dst = g_ed[e];

    float f = g_eef[e];
    float ssv = g_ss[src * 8 + l];
    float sdv = g_sd[dst * 8 + l];
    float sev = g_se[dst * 8 + l];
    const float4* hv = (const float4*)(g_ht + (size_t)src * 128);
    float4 v0 = hv[l];
    float4 v1 = hv[8 + l];
    float4 v2 = hv[16 + l];
    float4 v3 = hv[24 + l];

    float s = ssv + sdv + f * __ldg(We + l);
    s = fmaxf(s, 0.2f * s);
    float alpha = 0.125f * __expf(s) / sev;

    int hi = l >> 2;
    float4 acc;
    float a;
    a = __shfl_sync(0xffffffffu, alpha, 0 + hi, 8);
    acc.x = a * v0.x; acc.y = a * v0.y; acc.z = a * v0.z; acc.w = a * v0.w;
    a = __shfl_sync(0xffffffffu, alpha, 2 + hi, 8);
    acc.x += a * v1.x; acc.y += a * v1.y; acc.z += a * v1.z; acc.w += a * v1.w;
    a = __shfl_sync(0xffffffffu, alpha, 4 + hi, 8);
    acc.x += a * v2.x; acc.y += a * v2.y; acc.z += a * v2.z; acc.w += a * v2.w;
    a = __shfl_sync(0xffffffffu, alpha, 6 + hi, 8);
    acc.x += a * v3.x; acc.y += a * v3.y; acc.z += a * v3.z; acc.w += a * v3.w;

    acc.x += __shfl_xor_sync(0xffffffffu, acc.x, 4, 8);
    acc.y += __shfl_xor_sync(0xffffffffu, acc.y, 4, 8);
    acc.z += __shfl_xor_sync(0xffffffffu, acc.z, 4, 8);
    acc.w += __shfl_xor_sync(0xffffffffu, acc.w, 4, 8);
    if (hi == 0) red_add_v4(out + (size_t)dst * 16 + l * 4, acc);
}

// ---------------------------------------------------------------------------
extern "C" void kernel_launch(void* const* d_in, const int* in_sizes, int n_in,
                              void* d_out, int out_size) {
    const float* h    = (const float*)d_in[0];
    const int*   ei   = (const int*)d_in[1];
    const float* ef   = (const float*)d_in[2];
    const float* Wn   = (const float*)d_in[3];
    const float* We   = (const float*)d_in[4];
    const float* asrc = (const float*)d_in[5];
    const float* adst = (const float*)d_in[6];
    float* out = (float*)d_out;

    cudaFuncSetAttribute(k_gemm, cudaFuncAttributeMaxDynamicSharedMemorySize, SM_TOT);

    void* p = nullptr;
    cudaGetSymbolAddress(&p, g_se);
    cudaMemsetAsync(p, 0, (size_t)NN * 8 * sizeof(float));
    cudaGetSymbolAddress(&p, g_cnt);
    cudaMemsetAsync(p, 0, (size_t)NN * sizeof(int));
    cudaMemsetAsync(out, 0, (size_t)NN * 16 * sizeof(float));

    k_prepW<<<64, 256>>>(Wn);
    k_hist<<<EE / 256, 256>>>(ei);
    k_scanA<<<(NN + 255) / 256, 256>>>();
    k_scanB<<<1, 256>>>();
    k_scanC<<<(NN + 255) / 256, 256>>>();
    k_scat<<<EE / 256, 256>>>(ei, ef);
    k_gemm<<<(NN + 63) / 64, 256, SM_TOT>>>(h, asrc, adst);
    k_edgeA<<<(EE * 2) / 256, 256>>>(We);
    k_edgeB<<<(EE * 8) / 256, 256>>>(We, out);
}

// round 12
// speedup vs baseline: 1.2489x; 1.2489x over previous
#include <cuda_runtime.h>
#include <cuda_bf16.h>
#include <cuda_fp16.h>

#define NN 50000
#define EE 800000

// Scratch (no cudaMalloc allowed)
__device__ __half g_hth[NN * 128]; // h @ W_node, fp16, [N][H*F] (12.8MB)
__device__ float g_ss[NN * 8];     // per-node src attention scalar
__device__ float g_sd[NN * 8];     // per-node dst attention scalar
__device__ float g_se[NN * 8];     // sum of exp per (dst, head)
__device__ uint4 g_Bhi[2048];      // W^T hi bf16, [n=128][k=128] (32KB)
__device__ uint4 g_Blo[2048];      // W^T lo bf16

// ---------------- helpers ----------------
__device__ __forceinline__ void red_add_v4(float* p, float4 v) {
    asm volatile("red.global.add.v4.f32 [%0], {%1,%2,%3,%4};"
                 :: "l"(p), "f"(v.x), "f"(v.y), "f"(v.z), "f"(v.w) : "memory");
}
__device__ __forceinline__ unsigned smem_u32(const void* p) {
    unsigned a;
    asm("{ .reg .u64 t; cvta.to.shared.u64 t, %1; cvt.u32.u64 %0, t; }"
        : "=r"(a) : "l"(p));
    return a;
}
__device__ __forceinline__ void ldsm4(unsigned* r, unsigned addr) {
    asm volatile("ldmatrix.sync.aligned.m8n8.x4.shared.b16 {%0,%1,%2,%3}, [%4];"
                 : "=r"(r[0]), "=r"(r[1]), "=r"(r[2]), "=r"(r[3]) : "r"(addr));
}
__device__ __forceinline__ void mma_bf16(float* d, const unsigned* a,
                                         unsigned b0, unsigned b1) {
    asm volatile(
        "mma.sync.aligned.m16n8k16.row.col.f32.bf16.bf16.f32 "
        "{%0,%1,%2,%3}, {%4,%5,%6,%7}, {%8,%9}, {%0,%1,%2,%3};"
        : "+f"(d[0]), "+f"(d[1]), "+f"(d[2]), "+f"(d[3])
        : "r"(a[0]), "r"(a[1]), "r"(a[2]), "r"(a[3]), "r"(b0), "r"(b1));
}
__device__ __forceinline__ int swz(int c, int r) {
    return (c & 8) | ((c ^ r) & 7);
}
// unpack 8 halfs (uint4) -> 8 floats
__device__ __forceinline__ void h8_to_f8(uint4 u, float* f) {
    const __half2* hp = (const __half2*)&u;
#pragma unroll
    for (int i = 0; i < 4; i++) {
        float2 t = __half22float2(hp[i]);
        f[2 * i] = t.x;
        f[2 * i + 1] = t.y;
    }
}

// ---------------------------------------------------------------------------
// K0: prepack W^T hi/lo bf16 (B[n][k] = W[k][n]).
// ---------------------------------------------------------------------------
__global__ void k_prepW(const float* __restrict__ Wn) {
    int idx = blockIdx.x * 256 + threadIdx.x;
    if (idx >= 128 * 128) return;
    int n = idx >> 7, k = idx & 127;
    float v = Wn[k * 128 + n];
    __nv_bfloat16 hi = __float2bfloat16(v);
    __nv_bfloat16 lo = __float2bfloat16(v - __bfloat162float(hi));
    ((__nv_bfloat16*)g_Bhi)[n * 128 + k] = hi;
    ((__nv_bfloat16*)g_Blo)[n * 128 + k] = lo;
}

// ---------------------------------------------------------------------------
// K1: bf16 3-term GEMM via mma.sync (D = Ahi*Bhi + Ahi*Blo + Alo*Bhi).
// Epilogue: fp16 g_hth store + fused s_src/s_dst scalars (fp32 accumulators).
// CTA tile: 64 nodes x 128 cols; 8 warps = (row quarter rh, col half ch).
// ---------------------------------------------------------------------------
#define SM_AHI 0
#define SM_ALO 16384
#define SM_BHI 32768
#define SM_BLO 65536
#define SM_TOT 98304

__global__ __launch_bounds__(256, 2) void k_gemm(const float* __restrict__ hin,
                                                 const float* __restrict__ asrc,
                                                 const float* __restrict__ adst) {
    extern __shared__ char sm[];
    const unsigned sb = smem_u32(sm);
    const int tid = threadIdx.x, wid = tid >> 5, lid = tid & 31;
    const int n0 = blockIdx.x << 6;

    // B tiles (swizzled 16B-chunk copy)
#pragma unroll
    for (int i = 0; i < 8; i++) {
        int idx = tid + i * 256;
        int r = idx >> 4, c = idx & 15;
        int off = r * 256 + swz(c, r & 7) * 16;
        *(uint4*)(sm + SM_BHI + off) = g_Bhi[idx];
        *(uint4*)(sm + SM_BLO + off) = g_Blo[idx];
    }
    // A tiles: fp32 -> hi/lo bf16, swizzled
    const float4* h4 = (const float4*)hin;
#pragma unroll
    for (int i = 0; i < 8; i++) {
        int idx = tid + i * 256;
        int r = idx >> 5, c4 = idx & 31;
        int k = c4 << 2;
        float4 v = make_float4(0.f, 0.f, 0.f, 0.f);
        if (n0 + r < NN) v = h4[(size_t)(n0 + r) * 32 + c4];
        __nv_bfloat162 hA = __floats2bfloat162_rn(v.x, v.y);
        __nv_bfloat162 hB = __floats2bfloat162_rn(v.z, v.w);
        __nv_bfloat162 lA = __floats2bfloat162_rn(v.x - __bfloat162float(hA.x),
                                                  v.y - __bfloat162float(hA.y));
        __nv_bfloat162 lB = __floats2bfloat162_rn(v.z - __bfloat162float(hB.x),
                                                  v.w - __bfloat162float(hB.y));
        int off = r * 256 + swz(k >> 3, r & 7) * 16 + (k & 7) * 2;
        *(uint2*)(sm + SM_AHI + off) = make_uint2(*(unsigned*)&hA, *(unsigned*)&hB);
        *(uint2*)(sm + SM_ALO + off) = make_uint2(*(unsigned*)&lA, *(unsigned*)&lB);
    }
    __syncthreads();

    const int rh = wid & 3;
    const int ch = wid >> 2;

    float acc[8][4];
#pragma unroll
    for (int t = 0; t < 8; t++)
#pragma unroll
        for (int j = 0; j < 4; j++) acc[t][j] = 0.f;

    const int arow = rh * 16 + (lid & 15);
    const int bl = (lid & 7) + ((lid >> 4) << 3);
    const int bko = (lid >> 3) & 1;

#pragma unroll
    for (int ks = 0; ks < 8; ks++) {
        unsigned ahi[4], alo[4];
        {
            int c = ks * 2 + (lid >> 4);
            int aoff = arow * 256 + swz(c, arow & 7) * 16;
            ldsm4(ahi, sb + SM_AHI + aoff);
            ldsm4(alo, sb + SM_ALO + aoff);
        }
#pragma unroll
        for (int p = 0; p < 4; p++) {
            int n = ch * 64 + p * 16 + bl;
            int c = ks * 2 + bko;
            int boff = n * 256 + swz(c, n & 7) * 16;
            unsigned bhi[4], blo[4];
            ldsm4(bhi, sb + SM_BHI + boff);
            ldsm4(blo, sb + SM_BLO + boff);
            mma_bf16(acc[2 * p],     ahi, bhi[0], bhi[1]);
            mma_bf16(acc[2 * p],     ahi, blo[0], blo[1]);
            mma_bf16(acc[2 * p],     alo, bhi[0], bhi[1]);
            mma_bf16(acc[2 * p + 1], ahi, bhi[2], bhi[3]);
            mma_bf16(acc[2 * p + 1], ahi, blo[2], blo[3]);
            mma_bf16(acc[2 * p + 1], alo, bhi[2], bhi[3]);
        }
    }

    // --- epilogue: fp16 g_hth store + fused attention scalars ---
    const int r0 = n0 + rh * 16 + (lid >> 2);
    const int r1 = r0 + 8;
#pragma unroll
    for (int t = 0; t < 8; t++) {
        int gcol = ch * 64 + t * 8 + 2 * (lid & 3);
        if (r0 < NN) *(__half2*)(g_hth + (size_t)r0 * 128 + gcol) =
            __floats2half2_rn(acc[t][0], acc[t][1]);
        if (r1 < NN) *(__half2*)(g_hth + (size_t)r1 * 128 + gcol) =
            __floats2half2_rn(acc[t][2], acc[t][3]);
    }
    // heads owned by this warp: ch*4+u (u=0..3); head u uses t = 2u, 2u+1
    const int q2 = 2 * (lid & 3);
#pragma unroll
    for (int u = 0; u < 4; u++) {
        int hh = ch * 4 + u;
        const float* as = asrc + hh * 16;
        const float* ad = adst + hh * 16;
        float a0 = __ldg(as + q2),     a1 = __ldg(as + q2 + 1);
        float a2 = __ldg(as + 8 + q2), a3 = __ldg(as + 8 + q2 + 1);
        float b0 = __ldg(ad + q2),     b1 = __ldg(ad + q2 + 1);
        float b2 = __ldg(ad + 8 + q2), b3 = __ldg(ad + 8 + q2 + 1);
        float s0 = acc[2*u][0]*a0 + acc[2*u][1]*a1 + acc[2*u+1][0]*a2 + acc[2*u+1][1]*a3;
        float s1 = acc[2*u][2]*a0 + acc[2*u][3]*a1 + acc[2*u+1][2]*a2 + acc[2*u+1][3]*a3;
        float d0 = acc[2*u][0]*b0 + acc[2*u][1]*b1 + acc[2*u+1][0]*b2 + acc[2*u+1][1]*b3;
        float d1 = acc[2*u][2]*b0 + acc[2*u][3]*b1 + acc[2*u+1][2]*b2 + acc[2*u+1][3]*b3;
        s0 += __shfl_xor_sync(0xffffffffu, s0, 1);
        s0 += __shfl_xor_sync(0xffffffffu, s0, 2);
        s1 += __shfl_xor_sync(0xffffffffu, s1, 1);
        s1 += __shfl_xor_sync(0xffffffffu, s1, 2);
        d0 += __shfl_xor_sync(0xffffffffu, d0, 1);
        d0 += __shfl_xor_sync(0xffffffffu, d0, 2);
        d1 += __shfl_xor_sync(0xffffffffu, d1, 1);
        d1 += __shfl_xor_sync(0xffffffffu, d1, 2);
        if ((lid & 3) == 0) {
            if (r0 < NN) { g_ss[r0 * 8 + hh] = s0; g_sd[r0 * 8 + hh] = d0; }
            if (r1 < NN) { g_ss[r1 * 8 + hh] = s1; g_sd[r1 * 8 + hh] = d1; }
        }
    }
}

// ---------------------------------------------------------------------------
// K3: edge pass A — sum of exp(leaky_relu(logit)) per (dst, head).
// 2 threads/edge (4 heads each), 1 red.v4 per thread.
// ---------------------------------------------------------------------------
__global__ void k_edgeA(const int* __restrict__ ei,
                        const float* __restrict__ ef,
                        const float* __restrict__ We) {
    int gid = blockIdx.x * 256 + threadIdx.x;   // grid exact: (EE*2) % 256 == 0
    int e = gid >> 1;
    int half = gid & 1;
    int src = ei[e];
    int dst = ei[EE + e];
    float f = __ldg(ef + e);
    float4 s = ((const float4*)g_ss)[src * 2 + half];
    float4 d = ((const float4*)g_sd)[dst * 2 + half];
    float4 w = ((const float4*)We)[half];
    float4 x;
    x.x = s.x + d.x + f * w.x;
    x.y = s.y + d.y + f * w.y;
    x.z = s.z + d.z + f * w.z;
    x.w = s.w + d.w + f * w.w;
    x.x = __expf(fmaxf(x.x, 0.2f * x.x));
    x.y = __expf(fmaxf(x.y, 0.2f * x.y));
    x.z = __expf(fmaxf(x.z, 0.2f * x.z));
    x.w = __expf(fmaxf(x.w, 0.2f * x.w));
    red_add_v4(g_se + dst * 8 + half * 4, x);
}

// ---------------------------------------------------------------------------
// K4: edge pass B — fp16 gather (halved L2 traffic), fp32 math/atomics.
// 8 lanes/edge; lane l loads 16B chunks l and 8+l of the 256B fp16 row
// (fully coalesced 128B warp segments). Chunk c = head c>>1, feat-half c&1.
// Head-weighted via 2 shuffled alphas; head-reduction via xor-2 + xor-4
// (parity == feature-half preserved); lanes 0/1 issue 2 red.v4 each.
// ---------------------------------------------------------------------------
__global__ void k_edgeB(const int* __restrict__ ei,
                        const float* __restrict__ ef,
                        const float* __restrict__ We,
                        float* __restrict__ out) {
    int gid = blockIdx.x * 256 + threadIdx.x;  // grid exact: (EE*8) % 256 == 0
    int e = gid >> 3;
    int l = gid & 7;
    int src = ei[e];
    int dst = ei[EE + e];

    // independent gathers issued early
    float f = __ldg(ef + e);
    float ssv = g_ss[src * 8 + l];
    float sdv = g_sd[dst * 8 + l];
    float sev = g_se[dst * 8 + l];
    const uint4* hv = (const uint4*)(g_hth + (size_t)src * 128);
    uint4 ua = hv[l];        // head l>>1,      feat-half l&1
    uint4 ub = hv[8 + l];    // head 4+(l>>1),  feat-half l&1

    float s = ssv + sdv + f * __ldg(We + l);
    s = fmaxf(s, 0.2f * s);
    float alpha = 0.125f * __expf(s) / sev;   // this lane = head l

    float a0 = __shfl_sync(0xffffffffu, alpha, (l >> 1), 8);
    float a1 = __shfl_sync(0xffffffffu, alpha, 4 + (l >> 1), 8);

    float fa[8], fb[8], acc[8];
    h8_to_f8(ua, fa);
    h8_to_f8(ub, fb);
#pragma unroll
    for (int j = 0; j < 8; j++) acc[j] = a0 * fa[j] + a1 * fb[j];

    // reduce over head-groups (lanes of same parity cover all 8 heads)
#pragma unroll
    for (int j = 0; j < 8; j++) acc[j] += __shfl_xor_sync(0xffffffffu, acc[j], 2, 8);
#pragma unroll
    for (int j = 0; j < 8; j++) acc[j] += __shfl_xor_sync(0xffffffffu, acc[j], 4, 8);

    if (l < 2) {
        float* base = out + (size_t)dst * 16 + l * 8;
        red_add_v4(base,     make_float4(acc[0], acc[1], acc[2], acc[3]));
        red_add_v4(base + 4, make_float4(acc[4], acc[5], acc[6], acc[7]));
    }
}

// ---------------------------------------------------------------------------
extern "C" void kernel_launch(void* const* d_in, const int* in_sizes, int n_in,
                              void* d_out, int out_size) {
    const float* h    = (const float*)d_in[0];
    const int*   ei   = (const int*)d_in[1];
    const float* ef   = (const float*)d_in[2];
    const float* Wn   = (const float*)d_in[3];
    const float* We   = (const float*)d_in[4];
    const float* asrc = (const float*)d_in[5];
    const float* adst = (const float*)d_in[6];
    float* out = (float*)d_out;

    cudaFuncSetAttribute(k_gemm, cudaFuncAttributeMaxDynamicSharedMemorySize, SM_TOT);

    void* p = nullptr;
    cudaGetSymbolAddress(&p, g_se);
    cudaMemsetAsync(p, 0, (size_t)NN * 8 * sizeof(float));
    cudaMemsetAsync(out, 0, (size_t)NN * 16 * sizeof(float));

    k_prepW<<<64, 256>>>(Wn);
    k_gemm<<<(NN + 63) / 64, 256, SM_TOT>>>(h, asrc, adst);
    k_edgeA<<<(EE * 2) / 256, 256>>>(ei, ef, We);
    k_edgeB<<<(EE * 8) / 256, 256>>>(ei, ef, We, out);
}

// round 14
// speedup vs baseline: 1.3496x; 1.0806x over previous
#include <cuda_runtime.h>
#include <cuda_bf16.h>
#include <cuda_fp16.h>

#define NN 50000
#define EE 800000

// Scratch (no cudaMalloc allowed)
__device__ __half g_hth[NN * 128]; // h @ W_node, fp16, [N][H*F] (12.8MB)
__device__ float g_ss[NN * 8];     // per-node src attention scalar
__device__ float g_sd[NN * 8];     // per-node dst attention scalar
__device__ float g_se[NN * 8];     // sum of exp per (dst, head)
__device__ uint4 g_Bhi[2048];      // W^T hi bf16, [n=128][k=128] (32KB)
__device__ uint4 g_Blo[2048];      // W^T lo bf16

// ---------------- helpers ----------------
__device__ __forceinline__ void red_add_v4(float* p, float4 v) {
    asm volatile("red.global.add.v4.f32 [%0], {%1,%2,%3,%4};"
                 :: "l"(p), "f"(v.x), "f"(v.y), "f"(v.z), "f"(v.w) : "memory");
}
__device__ __forceinline__ unsigned smem_u32(const void* p) {
    unsigned a;
    asm("{ .reg .u64 t; cvta.to.shared.u64 t, %1; cvt.u32.u64 %0, t; }"
        : "=r"(a) : "l"(p));
    return a;
}
__device__ __forceinline__ void ldsm4(unsigned* r, unsigned addr) {
    asm volatile("ldmatrix.sync.aligned.m8n8.x4.shared.b16 {%0,%1,%2,%3}, [%4];"
                 : "=r"(r[0]), "=r"(r[1]), "=r"(r[2]), "=r"(r[3]) : "r"(addr));
}
__device__ __forceinline__ void mma_bf16(float* d, const unsigned* a,
                                         unsigned b0, unsigned b1) {
    asm volatile(
        "mma.sync.aligned.m16n8k16.row.col.f32.bf16.bf16.f32 "
        "{%0,%1,%2,%3}, {%4,%5,%6,%7}, {%8,%9}, {%0,%1,%2,%3};"
        : "+f"(d[0]), "+f"(d[1]), "+f"(d[2]), "+f"(d[3])
        : "r"(a[0]), "r"(a[1]), "r"(a[2]), "r"(a[3]), "r"(b0), "r"(b1));
}
__device__ __forceinline__ int swz(int c, int r) {
    return (c & 8) | ((c ^ r) & 7);
}

// ---------------------------------------------------------------------------
// K0: prepack W^T hi/lo bf16 (B[n][k] = W[k][n]).
// ---------------------------------------------------------------------------
__global__ void k_prepW(const float* __restrict__ Wn) {
    int idx = blockIdx.x * 256 + threadIdx.x;
    if (idx >= 128 * 128) return;
    int n = idx >> 7, k = idx & 127;
    float v = Wn[k * 128 + n];
    __nv_bfloat16 hi = __float2bfloat16(v);
    __nv_bfloat16 lo = __float2bfloat16(v - __bfloat162float(hi));
    ((__nv_bfloat16*)g_Bhi)[n * 128 + k] = hi;
    ((__nv_bfloat16*)g_Blo)[n * 128 + k] = lo;
}

// ---------------------------------------------------------------------------
// K1: bf16 3-term GEMM via mma.sync (D = Ahi*Bhi + Ahi*Blo + Alo*Bhi).
// Epilogue: fp16 g_hth store + fused s_src/s_dst scalars (fp32 accumulators).
// CTA tile: 64 nodes x 128 cols; 8 warps = (row quarter rh, col half ch).
// ---------------------------------------------------------------------------
#define SM_AHI 0
#define SM_ALO 16384
#define SM_BHI 32768
#define SM_BLO 65536
#define SM_TOT 98304

__global__ __launch_bounds__(256, 2) void k_gemm(const float* __restrict__ hin,
                                                 const float* __restrict__ asrc,
                                                 const float* __restrict__ adst) {
    extern __shared__ char sm[];
    const unsigned sb = smem_u32(sm);
    const int tid = threadIdx.x, wid = tid >> 5, lid = tid & 31;
    const int n0 = blockIdx.x << 6;

    // B tiles (swizzled 16B-chunk copy)
#pragma unroll
    for (int i = 0; i < 8; i++) {
        int idx = tid + i * 256;
        int r = idx >> 4, c = idx & 15;
        int off = r * 256 + swz(c, r & 7) * 16;
        *(uint4*)(sm + SM_BHI + off) = g_Bhi[idx];
        *(uint4*)(sm + SM_BLO + off) = g_Blo[idx];
    }
    // A tiles: fp32 -> hi/lo bf16, swizzled
    const float4* h4 = (const float4*)hin;
#pragma unroll
    for (int i = 0; i < 8; i++) {
        int idx = tid + i * 256;
        int r = idx >> 5, c4 = idx & 31;
        int k = c4 << 2;
        float4 v = make_float4(0.f, 0.f, 0.f, 0.f);
        if (n0 + r < NN) v = h4[(size_t)(n0 + r) * 32 + c4];
        __nv_bfloat162 hA = __floats2bfloat162_rn(v.x, v.y);
        __nv_bfloat162 hB = __floats2bfloat162_rn(v.z, v.w);
        __nv_bfloat162 lA = __floats2bfloat162_rn(v.x - __bfloat162float(hA.x),
                                                  v.y - __bfloat162float(hA.y));
        __nv_bfloat162 lB = __floats2bfloat162_rn(v.z - __bfloat162float(hB.x),
                                                  v.w - __bfloat162float(hB.y));
        int off = r * 256 + swz(k >> 3, r & 7) * 16 + (k & 7) * 2;
        *(uint2*)(sm + SM_AHI + off) = make_uint2(*(unsigned*)&hA, *(unsigned*)&hB);
        *(uint2*)(sm + SM_ALO + off) = make_uint2(*(unsigned*)&lA, *(unsigned*)&lB);
    }
    __syncthreads();

    const int rh = wid & 3;
    const int ch = wid >> 2;

    float acc[8][4];
#pragma unroll
    for (int t = 0; t < 8; t++)
#pragma unroll
        for (int j = 0; j < 4; j++) acc[t][j] = 0.f;

    const int arow = rh * 16 + (lid & 15);
    const int bl = (lid & 7) + ((lid >> 4) << 3);
    const int bko = (lid >> 3) & 1;

#pragma unroll
    for (int ks = 0; ks < 8; ks++) {
        unsigned ahi[4], alo[4];
        {
            int c = ks * 2 + (lid >> 4);
            int aoff = arow * 256 + swz(c, arow & 7) * 16;
            ldsm4(ahi, sb + SM_AHI + aoff);
            ldsm4(alo, sb + SM_ALO + aoff);
        }
#pragma unroll
        for (int p = 0; p < 4; p++) {
            int n = ch * 64 + p * 16 + bl;
            int c = ks * 2 + bko;
            int boff = n * 256 + swz(c, n & 7) * 16;
            unsigned bhi[4], blo[4];
            ldsm4(bhi, sb + SM_BHI + boff);
            ldsm4(blo, sb + SM_BLO + boff);
            mma_bf16(acc[2 * p],     ahi, bhi[0], bhi[1]);
            mma_bf16(acc[2 * p],     ahi, blo[0], blo[1]);
            mma_bf16(acc[2 * p],     alo, bhi[0], bhi[1]);
            mma_bf16(acc[2 * p + 1], ahi, bhi[2], bhi[3]);
            mma_bf16(acc[2 * p + 1], ahi, blo[2], blo[3]);
            mma_bf16(acc[2 * p + 1], alo, bhi[2], bhi[3]);
        }
    }

    // --- epilogue: fp16 g_hth store + fused attention scalars ---
    const int r0 = n0 + rh * 16 + (lid >> 2);
    const int r1 = r0 + 8;
#pragma unroll
    for (int t = 0; t < 8; t++) {
        int gcol = ch * 64 + t * 8 + 2 * (lid & 3);
        if (r0 < NN) *(__half2*)(g_hth + (size_t)r0 * 128 + gcol) =
            __floats2half2_rn(acc[t][0], acc[t][1]);
        if (r1 < NN) *(__half2*)(g_hth + (size_t)r1 * 128 + gcol) =
            __floats2half2_rn(acc[t][2], acc[t][3]);
    }
    // heads owned by this warp: ch*4+u (u=0..3); head u uses t = 2u, 2u+1
    const int q2 = 2 * (lid & 3);
#pragma unroll
    for (int u = 0; u < 4; u++) {
        int hh = ch * 4 + u;
        const float* as = asrc + hh * 16;
        const float* ad = adst + hh * 16;
        float a0 = __ldg(as + q2),     a1 = __ldg(as + q2 + 1);
        float a2 = __ldg(as + 8 + q2), a3 = __ldg(as + 8 + q2 + 1);
        float b0 = __ldg(ad + q2),     b1 = __ldg(ad + q2 + 1);
        float b2 = __ldg(ad + 8 + q2), b3 = __ldg(ad + 8 + q2 + 1);
        float s0 = acc[2*u][0]*a0 + acc[2*u][1]*a1 + acc[2*u+1][0]*a2 + acc[2*u+1][1]*a3;
        float s1 = acc[2*u][2]*a0 + acc[2*u][3]*a1 + acc[2*u+1][2]*a2 + acc[2*u+1][3]*a3;
        float d0 = acc[2*u][0]*b0 + acc[2*u][1]*b1 + acc[2*u+1][0]*b2 + acc[2*u+1][1]*b3;
        float d1 = acc[2*u][2]*b0 + acc[2*u][3]*b1 + acc[2*u+1][2]*b2 + acc[2*u+1][3]*b3;
        s0 += __shfl_xor_sync(0xffffffffu, s0, 1);
        s0 += __shfl_xor_sync(0xffffffffu, s0, 2);
        s1 += __shfl_xor_sync(0xffffffffu, s1, 1);
        s1 += __shfl_xor_sync(0xffffffffu, s1, 2);
        d0 += __shfl_xor_sync(0xffffffffu, d0, 1);
        d0 += __shfl_xor_sync(0xffffffffu, d0, 2);
        d1 += __shfl_xor_sync(0xffffffffu, d1, 1);
        d1 += __shfl_xor_sync(0xffffffffu, d1, 2);
        if ((lid & 3) == 0) {
            if (r0 < NN) { g_ss[r0 * 8 + hh] = s0; g_sd[r0 * 8 + hh] = d0; }
            if (r1 < NN) { g_ss[r1 * 8 + hh] = s1; g_sd[r1 * 8 + hh] = d1; }
        }
    }
}

// ---------------------------------------------------------------------------
// K3: edge pass A — sum of exp(leaky_relu(logit)) per (dst, head).
// 2 threads/edge (4 heads each), 1 red.v4 per thread.
// ---------------------------------------------------------------------------
__global__ void k_edgeA(const int* __restrict__ ei,
                        const float* __restrict__ ef,
                        const float* __restrict__ We) {
    int gid = blockIdx.x * 256 + threadIdx.x;   // grid exact: (EE*2) % 256 == 0
    int e = gid >> 1;
    int half = gid & 1;
    int src = ei[e];
    int dst = ei[EE + e];
    float f = __ldg(ef + e);
    float4 s = ((const float4*)g_ss)[src * 2 + half];
    float4 d = ((const float4*)g_sd)[dst * 2 + half];
    float4 w = ((const float4*)We)[half];
    float4 x;
    x.x = s.x + d.x + f * w.x;
    x.y = s.y + d.y + f * w.y;
    x.z = s.z + d.z + f * w.z;
    x.w = s.w + d.w + f * w.w;
    x.x = __expf(fmaxf(x.x, 0.2f * x.x));
    x.y = __expf(fmaxf(x.y, 0.2f * x.y));
    x.z = __expf(fmaxf(x.z, 0.2f * x.z));
    x.w = __expf(fmaxf(x.w, 0.2f * x.w));
    red_add_v4(g_se + dst * 8 + half * 4, x);
}

// ---------------------------------------------------------------------------
// K4: edge pass B — fp16 gather + HALF2 weighting/reduction (low instr count),
// fp32 only at the final atomic. 8 lanes/edge; lane l loads chunks l and 8+l
// (head l>>1 / 4+(l>>1), feat-half l&1). xor-2 + xor-4 HADD2 reduction leaves
// lane 0 = feats 0-7, lane 1 = feats 8-15 (summed over all 8 heads).
// ---------------------------------------------------------------------------
__global__ void k_edgeB(const int* __restrict__ ei,
                        const float* __restrict__ ef,
                        const float* __restrict__ We,
                        float* __restrict__ out) {
    int gid = blockIdx.x * 256 + threadIdx.x;  // grid exact: (EE*8) % 256 == 0
    int e = gid >> 3;
    int l = gid & 7;
    int src = ei[e];
    int dst = ei[EE + e];

    // independent gathers issued early
    float f = __ldg(ef + e);
    float ssv = g_ss[src * 8 + l];
    float sdv = g_sd[dst * 8 + l];
    float sev = g_se[dst * 8 + l];
    const uint4* hv = (const uint4*)(g_hth + (size_t)src * 128);
    uint4 ua = hv[l];        // head l>>1,      feat-half l&1
    uint4 ub = hv[8 + l];    // head 4+(l>>1),  feat-half l&1

    float s = ssv + sdv + f * __ldg(We + l);
    s = fmaxf(s, 0.2f * s);
    float alpha = 0.125f * __expf(s) / sev;   // this lane = head l

    float a0 = __shfl_sync(0xffffffffu, alpha, (l >> 1), 8);
    float a1 = __shfl_sync(0xffffffffu, alpha, 4 + (l >> 1), 8);
    __half2 a0h = __float2half2_rn(a0);
    __half2 a1h = __float2half2_rn(a1);

    const __half2* uah = (const __half2*)&ua;
    const __half2* ubh = (const __half2*)&ub;
    unsigned acc[4];
#pragma unroll
    for (int i = 0; i < 4; i++) {
        __half2 t = __hfma2(uah[i], a0h, __hmul2(ubh[i], a1h));
        acc[i] = *(unsigned*)&t;
    }
    // head reduction (parity == feat-half preserved)
#pragma unroll
    for (int i = 0; i < 4; i++) {
        unsigned o = __shfl_xor_sync(0xffffffffu, acc[i], 2, 8);
        __half2 t = __hadd2(*(__half2*)&acc[i], *(__half2*)&o);
        acc[i] = *(unsigned*)&t;
    }
#pragma unroll
    for (int i = 0; i < 4; i++) {
        unsigned o = __shfl_xor_sync(0xffffffffu, acc[i], 4, 8);
        __half2 t = __hadd2(*(__half2*)&acc[i], *(__half2*)&o);
        acc[i] = *(unsigned*)&t;
    }

    if (l < 2) {
        float2 f0 = __half22float2(*(__half2*)&acc[0]);
        float2 f1 = __half22float2(*(__half2*)&acc[1]);
        float2 f2 = __half22float2(*(__half2*)&acc[2]);
        float2 f3 = __half22float2(*(__half2*)&acc[3]);
        float* base = out + (size_t)dst * 16 + l * 8;
        red_add_v4(base,     make_float4(f0.x, f0.y, f1.x, f1.y));
        red_add_v4(base + 4, make_float4(f2.x, f2.y, f3.x, f3.y));
    }
}

// ---------------------------------------------------------------------------
extern "C" void kernel_launch(void* const* d_in, const int* in_sizes, int n_in,
                              void* d_out, int out_size) {
    const float* h    = (const float*)d_in[0];
    const int*   ei   = (const int*)d_in[1];
    const float* ef   = (const float*)d_in[2];
    const float* Wn   = (const float*)d_in[3];
    const float* We   = (const float*)d_in[4];
    const float* asrc = (const float*)d_in[5];
    const float* adst = (const float*)d_in[6];
    float* out = (float*)d_out;

    cudaFuncSetAttribute(k_gemm, cudaFuncAttributeMaxDynamicSharedMemorySize, SM_TOT);

    void* p = nullptr;
    cudaGetSymbolAddress(&p, g_se);
    cudaMemsetAsync(p, 0, (size_t)NN * 8 * sizeof(float));
    cudaMemsetAsync(out, 0, (size_t)NN * 16 * sizeof(float));

    k_prepW<<<64, 256>>>(Wn);
    k_gemm<<<(NN + 63) / 64, 256, SM_TOT>>>(h, asrc, adst);
    k_edgeA<<<(EE * 2) / 256, 256>>>(ei, ef, We);
    k_edgeB<<<(EE * 8) / 256, 256>>>(ei, ef, We, out);
}